// round 13
// baseline (speedup 1.0000x reference)
#include <cuda_runtime.h>
#include <cuda_fp16.h>
#include <cstdint>

#define HD 128
#define NT 4
#define ET 8
#define N_MAX 50000
#define E_MAX 800000
#define NPAD_MAX (N_MAX + NT*128 + 256)

// ---- scratch (__device__ globals) ----
__device__ float    g_Q[N_MAX*HD];
__device__ uint32_t g_Kh[N_MAX*HD/2];                 // bf16x2 pairs
__device__ uint32_t g_Vh[N_MAX*HD/2];                 // fp16x2 pairs
__device__ uint32_t g_Ph[(size_t)N_MAX*ET*HD/2];      // bf16x2, layout [n][t][k]
__device__ float    g_WT[3*NT*HD*HD];                 // W_Q/K/V transposed
__device__ int      g_perm[NPAD_MAX];
__device__ int      g_count[NT];
__device__ int      g_cursor[NT];
__device__ int      g_offal[NT+1];
// CSR over dst: (src, ety) pairs
__device__ int      g_dcnt[N_MAX];
__device__ int      g_dcur[N_MAX];
__device__ int      g_epos[N_MAX+1];
__device__ int2     g_csr[E_MAX];
__device__ int      g_bsum[256];
__device__ int      g_boff[256];

// ================= helpers =================
__device__ __forceinline__ uint32_t f2tf32(float f) {
    uint32_t r; asm("cvt.rna.tf32.f32 %0, %1;" : "=r"(r) : "f"(f)); return r;
}
__device__ __forceinline__ void mma_tf32(float* d, const uint32_t* a, const uint32_t* b) {
    asm volatile("mma.sync.aligned.m16n8k8.row.col.f32.tf32.tf32.f32 "
        "{%0,%1,%2,%3}, {%4,%5,%6,%7}, {%8,%9}, {%0,%1,%2,%3};"
        : "+f"(d[0]), "+f"(d[1]), "+f"(d[2]), "+f"(d[3])
        : "r"(a[0]), "r"(a[1]), "r"(a[2]), "r"(a[3]), "r"(b[0]), "r"(b[1]));
}
__device__ __forceinline__ uint32_t pack_bf16x2(float a, float b) {
    uint32_t r; asm("cvt.rn.bf16x2.f32 %0, %1, %2;" : "=r"(r) : "f"(b), "f"(a)); return r;
}
__device__ __forceinline__ float2 bf2f(uint32_t u) {
    float2 r;
    r.x = __uint_as_float(u << 16);
    r.y = __uint_as_float(u & 0xFFFF0000u);
    return r;
}
__device__ __forceinline__ uint32_t pack_f16x2(float a, float b) {
    __half2 h = __floats2half2_rn(a, b);
    return *(uint32_t*)&h;
}
__device__ __forceinline__ float2 f16_2f(uint32_t u) {
    __half2 h = *(__half2*)&u;
    return __half22float2(h);
}

// Two-stage K-chunked tiles: 128 rows x 16 k-cols, stride 20.
// Fragment load bank = (20g + t4) mod 32 -> all 32 banks covered: conflict-free.
// 2 stages x (A+B) x 10KB = 40KB static smem.
#define SAC 20
#define KCH 16
#define NCHUNK (HD / KCH)

// ================= setup kernels =================
// init + W transpose fused (both depend only on inputs)
__global__ void k_init(const float* __restrict__ WQ, const float* __restrict__ WK,
                       const float* __restrict__ WV, int N) {
    int i = blockIdx.x * blockDim.x + threadIdx.x;
    if (i < N) { g_dcnt[i] = 0; g_dcur[i] = 0; }
    if (i < N + NT * 128) g_perm[i] = -1;
    if (i < NT) { g_count[i] = 0; g_cursor[i] = 0; }
    if (i < 3 * NT * HD * HD) {
        int m = i >> 14;
        int r = i & 16383;
        int j = r >> 7;
        int k = r & 127;
        const float* W = ((m < NT) ? WQ : (m < 2 * NT) ? WK : WV) + (size_t)(m & (NT - 1)) * HD * HD;
        g_WT[(size_t)m * HD * HD + j * HD + k] = W[k * HD + j];
    }
}

__global__ void k_hist(const int* __restrict__ nty, const int* __restrict__ dst, int N, int E) {
    __shared__ int c[NT];
    int tid = threadIdx.x;
    int i = blockIdx.x * blockDim.x + tid;
    if (tid < NT) c[tid] = 0;
    __syncthreads();
    if (i < N) atomicAdd(&c[nty[i]], 1);
    if (i < E) atomicAdd(&g_dcnt[dst[i]], 1);
    __syncthreads();
    if (tid < NT && c[tid] > 0) atomicAdd(&g_count[tid], c[tid]);
}

__global__ void k_prefix() {
    int acc = 0;
    for (int t = 0; t < NT; t++) {
        g_offal[t] = acc;
        acc += ((g_count[t] + 127) / 128) * 128;
    }
    g_offal[NT] = acc;
}

__global__ void k_scatter(const int* __restrict__ nty, int N) {
    __shared__ int cnt[NT];
    __shared__ int base[NT];
    int tid = threadIdx.x;
    int i = blockIdx.x * blockDim.x + tid;
    if (tid < NT) cnt[tid] = 0;
    __syncthreads();
    int t = -1, r = 0;
    if (i < N) { t = nty[i]; r = atomicAdd(&cnt[t], 1); }
    __syncthreads();
    if (tid < NT) base[tid] = (cnt[tid] > 0) ? atomicAdd(&g_cursor[tid], cnt[tid]) : 0;
    __syncthreads();
    if (i < N) g_perm[g_offal[t] + base[t] + r] = i;
}

__global__ void k_scan_block(int N) {
    __shared__ int sh[256];
    int i = blockIdx.x * 256 + threadIdx.x;
    int v = (i < N) ? g_dcnt[i] : 0;
    sh[threadIdx.x] = v; __syncthreads();
    for (int o = 1; o < 256; o <<= 1) {
        int t = (threadIdx.x >= o) ? sh[threadIdx.x - o] : 0;
        __syncthreads(); sh[threadIdx.x] += t; __syncthreads();
    }
    if (i < N) g_epos[i] = sh[threadIdx.x] - v;
    if (threadIdx.x == 255) g_bsum[blockIdx.x] = sh[255];
}
__global__ void k_scan_top(int nb, int E, int N) {
    __shared__ int sh[256];
    int v = (threadIdx.x < nb) ? g_bsum[threadIdx.x] : 0;
    sh[threadIdx.x] = v; __syncthreads();
    for (int o = 1; o < 256; o <<= 1) {
        int t = (threadIdx.x >= o) ? sh[threadIdx.x - o] : 0;
        __syncthreads(); sh[threadIdx.x] += t; __syncthreads();
    }
    if (threadIdx.x < nb) g_boff[threadIdx.x] = sh[threadIdx.x] - v;
    if (threadIdx.x == 0) g_epos[N] = E;
}
__global__ void k_scan_add(int N) {
    int i = blockIdx.x * 256 + threadIdx.x;
    if (i < N) g_epos[i] += g_boff[blockIdx.x];
}
__global__ void k_escatter(const int* __restrict__ src, const int* __restrict__ dst,
                           const int* __restrict__ ety, int E) {
    int e = blockIdx.x * blockDim.x + threadIdx.x;
    if (e < E) {
        int d = dst[e];
        int p = atomicAdd(&g_dcur[d], 1);
        g_csr[g_epos[d] + p] = make_int2(src[e], ety[e]);
    }
}

// ================= tf32 mma GEMMs (2-stage double-buffered chunks) =================
__device__ __forceinline__ void gemm_chunk_compute(
    const uint32_t* As, const uint32_t* Bs, float acc[4][4][4],
    int mw, int nw, int g, int t4)
{
    #pragma unroll
    for (int k0 = 0; k0 < KCH; k0 += 8) {
        uint32_t af[4][4];
        #pragma unroll
        for (int mi = 0; mi < 4; mi++) {
            int row = mw * 64 + mi * 16;
            af[mi][0] = As[(row + g) * SAC + k0 + t4];
            af[mi][1] = As[(row + g + 8) * SAC + k0 + t4];
            af[mi][2] = As[(row + g) * SAC + k0 + t4 + 4];
            af[mi][3] = As[(row + g + 8) * SAC + k0 + t4 + 4];
        }
        uint32_t bf[4][2];
        #pragma unroll
        for (int ni = 0; ni < 4; ni++) {
            int col = nw * 32 + ni * 8;
            bf[ni][0] = Bs[(col + g) * SAC + k0 + t4];
            bf[ni][1] = Bs[(col + g) * SAC + k0 + t4 + 4];
        }
        #pragma unroll
        for (int mi = 0; mi < 4; mi++)
            #pragma unroll
            for (int ni = 0; ni < 4; ni++)
                mma_tf32(acc[mi][ni], af[mi], bf[ni]);
    }
}

// chunk = 128 rows x 16 cols: 512 float4, 2 per thread per matrix
__device__ __forceinline__ void store_chunk(uint32_t* As, uint32_t* Bs,
                                            const float4* pa, const float4* pb, int tid) {
    #pragma unroll
    for (int i = 0; i < 2; i++) {
        int idx = tid + i * 256;
        int r = idx >> 2, q = idx & 3;
        float4 v = pa[i];
        *(uint4*)&As[r * SAC + q * 4] = make_uint4(f2tf32(v.x), f2tf32(v.y), f2tf32(v.z), f2tf32(v.w));
        float4 b = pb[i];
        *(uint4*)&Bs[r * SAC + q * 4] = make_uint4(f2tf32(b.x), f2tf32(b.y), f2tf32(b.z), f2tf32(b.w));
    }
}

// QKV: A = gathered x rows (one node type per 128-tile); loop Q/K/V; 2-stage chunks.
__global__ __launch_bounds__(256) void k_qkv_mma(const float* __restrict__ x, int N) {
    __shared__ uint32_t Asb[2][128 * SAC];
    __shared__ uint32_t Bsb[2][128 * SAC];
    __shared__ int rows[128];

    int tid = threadIdx.x;
    int wid = tid >> 5, lane = tid & 31;
    int g = lane >> 2, t4 = lane & 3;
    int mw = wid & 1, nw = wid >> 1;
    int base = blockIdx.x * 128;

    int ty = NT - 1;
    #pragma unroll
    for (int i = 0; i < NT; i++)
        if (base >= g_offal[i] && base < g_offal[i + 1]) ty = i;
    int total = g_offal[NT];
    if (tid < 128) {
        int gi = base + tid;
        rows[tid] = (gi < total) ? g_perm[gi] : -1;
    }
    __syncthreads();

    int lr0 = tid >> 2, lq0 = (tid & 3) * 4;
    int lr1 = (tid + 256) >> 2, lq1 = ((tid + 256) & 3) * 4;
    int node0 = rows[lr0], node1 = rows[lr1];

    for (int mat = 0; mat < 3; mat++) {
        const float* Wt = g_WT + (size_t)(mat * NT + ty) * HD * HD;

        float acc[4][4][4];
        #pragma unroll
        for (int mi = 0; mi < 4; mi++)
            #pragma unroll
            for (int ni = 0; ni < 4; ni++)
                #pragma unroll
                for (int r = 0; r < 4; r++) acc[mi][ni][r] = 0.0f;

        float4 pa[2], pb[2];
        // load chunk 0, store to buf0, load chunk 1
        pa[0] = (node0 >= 0) ? *(const float4*)(x + (size_t)node0 * HD + lq0) : make_float4(0,0,0,0);
        pa[1] = (node1 >= 0) ? *(const float4*)(x + (size_t)node1 * HD + lq1) : make_float4(0,0,0,0);
        pb[0] = *(const float4*)(Wt + (size_t)lr0 * HD + lq0);
        pb[1] = *(const float4*)(Wt + (size_t)lr1 * HD + lq1);
        store_chunk(Asb[0], Bsb[0], pa, pb, tid);
        pa[0] = (node0 >= 0) ? *(const float4*)(x + (size_t)node0 * HD + KCH + lq0) : make_float4(0,0,0,0);
        pa[1] = (node1 >= 0) ? *(const float4*)(x + (size_t)node1 * HD + KCH + lq1) : make_float4(0,0,0,0);
        pb[0] = *(const float4*)(Wt + (size_t)lr0 * HD + KCH + lq0);
        pb[1] = *(const float4*)(Wt + (size_t)lr1 * HD + KCH + lq1);
        __syncthreads();

        for (int ch = 0; ch < NCHUNK; ch++) {
            int cur = ch & 1;
            if (ch + 1 < NCHUNK) {
                store_chunk(Asb[1 - cur], Bsb[1 - cur], pa, pb, tid);
                if (ch + 2 < NCHUNK) {
                    int k0 = (ch + 2) * KCH;
                    pa[0] = (node0 >= 0) ? *(const float4*)(x + (size_t)node0 * HD + k0 + lq0) : make_float4(0,0,0,0);
                    pa[1] = (node1 >= 0) ? *(const float4*)(x + (size_t)node1 * HD + k0 + lq1) : make_float4(0,0,0,0);
                    pb[0] = *(const float4*)(Wt + (size_t)lr0 * HD + k0 + lq0);
                    pb[1] = *(const float4*)(Wt + (size_t)lr1 * HD + k0 + lq1);
                }
            }
            gemm_chunk_compute(Asb[cur], Bsb[cur], acc, mw, nw, g, t4);
            __syncthreads();
        }

        #pragma unroll
        for (int mi = 0; mi < 4; mi++) {
            int r0 = mw * 64 + mi * 16 + g;
            int n0 = rows[r0], n1 = rows[r0 + 8];
            #pragma unroll
            for (int ni = 0; ni < 4; ni++) {
                int col = nw * 32 + ni * 8 + t4 * 2;
                if (mat == 0) {
                    if (n0 >= 0) *(float2*)(g_Q + (size_t)n0 * HD + col) = make_float2(acc[mi][ni][0], acc[mi][ni][1]);
                    if (n1 >= 0) *(float2*)(g_Q + (size_t)n1 * HD + col) = make_float2(acc[mi][ni][2], acc[mi][ni][3]);
                } else if (mat == 1) {  // K -> bf16x2
                    if (n0 >= 0) g_Kh[(size_t)n0 * (HD/2) + (col >> 1)] = pack_bf16x2(acc[mi][ni][0], acc[mi][ni][1]);
                    if (n1 >= 0) g_Kh[(size_t)n1 * (HD/2) + (col >> 1)] = pack_bf16x2(acc[mi][ni][2], acc[mi][ni][3]);
                } else {                // V -> fp16x2
                    if (n0 >= 0) g_Vh[(size_t)n0 * (HD/2) + (col >> 1)] = pack_f16x2(acc[mi][ni][0], acc[mi][ni][1]);
                    if (n1 >= 0) g_Vh[(size_t)n1 * (HD/2) + (col >> 1)] = pack_f16x2(acc[mi][ni][2], acc[mi][ni][3]);
                }
            }
        }
    }
}

// P: A = g_Q rows; loop 8 edge types; 2-stage chunks; output bf16x2 [n][t][k].
__global__ __launch_bounds__(256) void k_p_mma(const float* __restrict__ We, int N) {
    __shared__ uint32_t Asb[2][128 * SAC];
    __shared__ uint32_t Bsb[2][128 * SAC];

    int tid = threadIdx.x;
    int wid = tid >> 5, lane = tid & 31;
    int g = lane >> 2, t4 = lane & 3;
    int mw = wid & 1, nw = wid >> 1;
    int base = blockIdx.x * 128;

    int lr0 = tid >> 2, lq0 = (tid & 3) * 4;
    int lr1 = (tid + 256) >> 2, lq1 = ((tid + 256) & 3) * 4;
    int nA0 = base + lr0, nA1 = base + lr1;
    bool v0 = nA0 < N, v1 = nA1 < N;

    for (int t = 0; t < ET; t++) {
        const float* Wt = We + (size_t)t * HD * HD;

        float acc[4][4][4];
        #pragma unroll
        for (int mi = 0; mi < 4; mi++)
            #pragma unroll
            for (int ni = 0; ni < 4; ni++)
                #pragma unroll
                for (int r = 0; r < 4; r++) acc[mi][ni][r] = 0.0f;

        float4 pa[2], pb[2];
        pa[0] = v0 ? *(const float4*)(g_Q + (size_t)nA0 * HD + lq0) : make_float4(0,0,0,0);
        pa[1] = v1 ? *(const float4*)(g_Q + (size_t)nA1 * HD + lq1) : make_float4(0,0,0,0);
        pb[0] = *(const float4*)(Wt + (size_t)lr0 * HD + lq0);
        pb[1] = *(const float4*)(Wt + (size_t)lr1 * HD + lq1);
        store_chunk(Asb[0], Bsb[0], pa, pb, tid);
        pa[0] = v0 ? *(const float4*)(g_Q + (size_t)nA0 * HD + KCH + lq0) : make_float4(0,0,0,0);
        pa[1] = v1 ? *(const float4*)(g_Q + (size_t)nA1 * HD + KCH + lq1) : make_float4(0,0,0,0);
        pb[0] = *(const float4*)(Wt + (size_t)lr0 * HD + KCH + lq0);
        pb[1] = *(const float4*)(Wt + (size_t)lr1 * HD + KCH + lq1);
        __syncthreads();

        for (int ch = 0; ch < NCHUNK; ch++) {
            int cur = ch & 1;
            if (ch + 1 < NCHUNK) {
                store_chunk(Asb[1 - cur], Bsb[1 - cur], pa, pb, tid);
                if (ch + 2 < NCHUNK) {
                    int k0 = (ch + 2) * KCH;
                    pa[0] = v0 ? *(const float4*)(g_Q + (size_t)nA0 * HD + k0 + lq0) : make_float4(0,0,0,0);
                    pa[1] = v1 ? *(const float4*)(g_Q + (size_t)nA1 * HD + k0 + lq1) : make_float4(0,0,0,0);
                    pb[0] = *(const float4*)(Wt + (size_t)lr0 * HD + k0 + lq0);
                    pb[1] = *(const float4*)(Wt + (size_t)lr1 * HD + k0 + lq1);
                }
            }
            gemm_chunk_compute(Asb[cur], Bsb[cur], acc, mw, nw, g, t4);
            __syncthreads();
        }

        #pragma unroll
        for (int mi = 0; mi < 4; mi++) {
            int r0 = mw * 64 + mi * 16 + g;
            int node0 = base + r0, node1 = base + r0 + 8;
            #pragma unroll
            for (int ni = 0; ni < 4; ni++) {
                int col = nw * 32 + ni * 8 + t4 * 2;
                if (node0 < N) g_Ph[((size_t)node0 * ET + t) * (HD/2) + (col >> 1)] = pack_bf16x2(acc[mi][ni][0], acc[mi][ni][1]);
                if (node1 < N) g_Ph[((size_t)node1 * ET + t) * (HD/2) + (col >> 1)] = pack_bf16x2(acc[mi][ni][2], acc[mi][ni][3]);
            }
        }
    }
}

// ================= fused single-pass edge kernel (x4, fp16 V) =================
__global__ __launch_bounds__(256) void k_edge(const float* __restrict__ mu,
                                              float* __restrict__ out, int N) {
    __shared__ float Psh[8][ET][HD];   // 32KB

    int wid = threadIdx.x >> 5;
    int l = threadIdx.x & 31;
    int n = blockIdx.x * 8 + wid;
    if (n >= N) return;

    const float SCALE = 0.08838834764831845f;  // 1/sqrt(128)

    #pragma unroll
    for (int t = 0; t < ET; t++) {
        float m = mu[t] * SCALE;
        uint2 u = *(const uint2*)(g_Ph + ((size_t)n * ET + t) * (HD/2) + l * 2);
        float2 p0 = bf2f(u.x), p1 = bf2f(u.y);
        Psh[wid][t][l*4 + 0] = p0.x * m;
        Psh[wid][t][l*4 + 1] = p0.y * m;
        Psh[wid][t][l*4 + 2] = p1.x * m;
        Psh[wid][t][l*4 + 3] = p1.y * m;
    }
    __syncwarp();

    int s0 = g_epos[n], s1 = g_epos[n + 1];

    float sum = 0.0f;
    float4 acc = make_float4(0.f, 0.f, 0.f, 0.f);
    int i = s0;

    for (; i + 3 < s1; i += 4) {
        int2 e0 = g_csr[i];
        int2 e1 = g_csr[i + 1];
        int2 e2 = g_csr[i + 2];
        int2 e3 = g_csr[i + 3];
        uint2 u0 = *(const uint2*)(g_Kh + (size_t)e0.x * (HD/2) + l * 2);
        uint2 u1 = *(const uint2*)(g_Kh + (size_t)e1.x * (HD/2) + l * 2);
        uint2 u2 = *(const uint2*)(g_Kh + (size_t)e2.x * (HD/2) + l * 2);
        uint2 u3 = *(const uint2*)(g_Kh + (size_t)e3.x * (HD/2) + l * 2);
        uint2 y0 = *(const uint2*)(g_Vh + (size_t)e0.x * (HD/2) + l * 2);
        uint2 y1 = *(const uint2*)(g_Vh + (size_t)e1.x * (HD/2) + l * 2);
        uint2 y2 = *(const uint2*)(g_Vh + (size_t)e2.x * (HD/2) + l * 2);
        uint2 y3 = *(const uint2*)(g_Vh + (size_t)e3.x * (HD/2) + l * 2);

        float2 a00 = bf2f(u0.x), a01 = bf2f(u0.y);
        float2 a10 = bf2f(u1.x), a11 = bf2f(u1.y);
        float2 a20 = bf2f(u2.x), a21 = bf2f(u2.y);
        float2 a30 = bf2f(u3.x), a31 = bf2f(u3.y);
        const float* p0 = &Psh[wid][e0.y][l*4];
        const float* p1 = &Psh[wid][e1.y][l*4];
        const float* p2 = &Psh[wid][e2.y][l*4];
        const float* p3 = &Psh[wid][e3.y][l*4];
        float v0 = a00.x * p0[0] + a00.y * p0[1] + a01.x * p0[2] + a01.y * p0[3];
        float v1 = a10.x * p1[0] + a10.y * p1[1] + a11.x * p1[2] + a11.y * p1[3];
        float v2 = a20.x * p2[0] + a20.y * p2[1] + a21.x * p2[2] + a21.y * p2[3];
        float v3 = a30.x * p3[0] + a30.y * p3[1] + a31.x * p3[2] + a31.y * p3[3];
        #pragma unroll
        for (int o = 16; o > 0; o >>= 1) {
            v0 += __shfl_xor_sync(0xffffffffu, v0, o);
            v1 += __shfl_xor_sync(0xffffffffu, v1, o);
            v2 += __shfl_xor_sync(0xffffffffu, v2, o);
            v3 += __shfl_xor_sync(0xffffffffu, v3, o);
        }
        float ex0 = __expf(v0);
        float ex1 = __expf(v1);
        float ex2 = __expf(v2);
        float ex3 = __expf(v3);
        sum += (ex0 + ex1) + (ex2 + ex3);
        float2 w0a = f16_2f(y0.x), w0b = f16_2f(y0.y);
        float2 w1a = f16_2f(y1.x), w1b = f16_2f(y1.y);
        float2 w2a = f16_2f(y2.x), w2b = f16_2f(y2.y);
        float2 w3a = f16_2f(y3.x), w3b = f16_2f(y3.y);
        acc.x += ex0 * w0a.x + ex1 * w1a.x + ex2 * w2a.x + ex3 * w3a.x;
        acc.y += ex0 * w0a.y + ex1 * w1a.y + ex2 * w2a.y + ex3 * w3a.y;
        acc.z += ex0 * w0b.x + ex1 * w1b.x + ex2 * w2b.x + ex3 * w3b.x;
        acc.w += ex0 * w0b.y + ex1 * w1b.y + ex2 * w2b.y + ex3 * w3b.y;
    }
    for (; i < s1; i++) {
        int2 e = g_csr[i];
        uint2 u = *(const uint2*)(g_Kh + (size_t)e.x * (HD/2) + l * 2);
        uint2 y = *(const uint2*)(g_Vh + (size_t)e.x * (HD/2) + l * 2);
        float2 k0 = bf2f(u.x), k1 = bf2f(u.y);
        const float* p = &Psh[wid][e.y][l*4];
        float v = k0.x * p[0] + k0.y * p[1] + k1.x * p[2] + k1.y * p[3];
        #pragma unroll
        for (int o = 16; o > 0; o >>= 1) v += __shfl_xor_sync(0xffffffffu, v, o);
        float ex = __expf(v);
        sum += ex;
        float2 wa = f16_2f(y.x), wb = f16_2f(y.y);
        acc.x += ex * wa.x; acc.y += ex * wa.y; acc.z += ex * wb.x; acc.w += ex * wb.y;
    }
    float inv = 1.0f / (sum + 1e-10f);
    acc.x *= inv; acc.y *= inv; acc.z *= inv; acc.w *= inv;
    *((float4*)(out + (size_t)n * HD) + l) = acc;
}

extern "C" void kernel_launch(void* const* d_in, const int* in_sizes, int n_in,
                              void* d_out, int out_size) {
    const float* x   = (const float*)d_in[0];
    const int*   ei  = (const int*)  d_in[1];
    const int*   ety = (const int*)  d_in[2];
    const int*   nty = (const int*)  d_in[3];
    const float* WQ  = (const float*)d_in[4];
    const float* WK  = (const float*)d_in[5];
    const float* WV  = (const float*)d_in[6];
    const float* We  = (const float*)d_in[7];
    const float* mu  = (const float*)d_in[8];
    float* out = (float*)d_out;

    int N = in_sizes[3];
    int E = in_sizes[2];
    const int* src = ei;
    const int* dst = ei + E;

    int nb = (N + 255) / 256;

    k_init<<<(3 * NT * HD * HD + 255) / 256, 256>>>(WQ, WK, WV, N);
    k_hist<<<(E + 255) / 256, 256>>>(nty, dst, N, E);
    k_prefix<<<1, 1>>>();
    k_scatter<<<(N + 255) / 256, 256>>>(nty, N);

    k_scan_block<<<nb, 256>>>(N);
    k_scan_top<<<1, 256>>>(nb, E, N);
    k_scan_add<<<nb, 256>>>(N);
    k_escatter<<<(E + 255) / 256, 256>>>(src, dst, ety, E);

    k_qkv_mma<<<(N + 127) / 128 + NT, 256>>>(x, N);
    k_p_mma<<<(N + 127) / 128, 256>>>(We, N);

    k_edge<<<(N + 7) / 8, 256>>>(mu, out, N);
}

// round 14
// speedup vs baseline: 1.1380x; 1.1380x over previous
#include <cuda_runtime.h>
#include <cstdint>

#define HD 128
#define NT 4
#define ET 8
#define N_MAX 50000
#define E_MAX 800000
#define NPAD_MAX (N_MAX + NT*128 + 256)

// ---- scratch (__device__ globals) ----
__device__ float    g_Q[N_MAX*HD];
__device__ uint32_t g_Kh[N_MAX*HD/2];                 // bf16x2 pairs
__device__ float    g_V[N_MAX*HD];
__device__ uint32_t g_Ph[(size_t)N_MAX*ET*HD/2];      // bf16x2, layout [n][t][k]
__device__ float    g_WT[3*NT*HD*HD];                 // W_Q/K/V transposed
__device__ int      g_perm[NPAD_MAX];
__device__ int      g_count[NT];
__device__ int      g_cursor[NT];
__device__ int      g_offal[NT+1];
// CSR over dst: (src, ety) pairs
__device__ int      g_dcnt[N_MAX];
__device__ int      g_dcur[N_MAX];
__device__ int      g_epos[N_MAX+1];
__device__ int2     g_csr[E_MAX];
__device__ int      g_bsum[256];
__device__ int      g_boff[256];

// ================= helpers =================
__device__ __forceinline__ uint32_t f2tf32(float f) {
    uint32_t r; asm("cvt.rna.tf32.f32 %0, %1;" : "=r"(r) : "f"(f)); return r;
}
__device__ __forceinline__ void mma_tf32(float* d, const uint32_t* a, const uint32_t* b) {
    asm volatile("mma.sync.aligned.m16n8k8.row.col.f32.tf32.tf32.f32 "
        "{%0,%1,%2,%3}, {%4,%5,%6,%7}, {%8,%9}, {%0,%1,%2,%3};"
        : "+f"(d[0]), "+f"(d[1]), "+f"(d[2]), "+f"(d[3])
        : "r"(a[0]), "r"(a[1]), "r"(a[2]), "r"(a[3]), "r"(b[0]), "r"(b[1]));
}
__device__ __forceinline__ void mma_bf16(float* d, const uint32_t* a, const uint32_t* b) {
    asm volatile("mma.sync.aligned.m16n8k16.row.col.f32.bf16.bf16.f32 "
        "{%0,%1,%2,%3}, {%4,%5,%6,%7}, {%8,%9}, {%0,%1,%2,%3};"
        : "+f"(d[0]), "+f"(d[1]), "+f"(d[2]), "+f"(d[3])
        : "r"(a[0]), "r"(a[1]), "r"(a[2]), "r"(a[3]), "r"(b[0]), "r"(b[1]));
}
__device__ __forceinline__ uint32_t pack_bf16x2(float a, float b) {
    uint32_t r; asm("cvt.rn.bf16x2.f32 %0, %1, %2;" : "=r"(r) : "f"(b), "f"(a)); return r;
}
__device__ __forceinline__ float2 bf2f(uint32_t u) {
    float2 r;
    r.x = __uint_as_float(u << 16);
    r.y = __uint_as_float(u & 0xFFFF0000u);
    return r;
}

// tf32 tiles (QKV): 128 rows x 32 k-cols, stride 36 (banks (4g+t4): conflict-free)
#define SAC 36
#define KCH 32
#define NCHUNK (HD / KCH)
// bf16 tiles (P): 128 rows x 16 bf16x2-pairs per chunk, stride 20
// fragment banks (20g + t4) mod 32 -> {0,20,8,28,16,4,24,12}+{0..3} = all 32: conflict-free
#define SB 20

// ================= setup kernels =================
__global__ void k_init(int N) {
    int i = blockIdx.x * blockDim.x + threadIdx.x;
    if (i < N) { g_dcnt[i] = 0; g_dcur[i] = 0; }
    if (i < N + NT * 128) g_perm[i] = -1;
    if (i < NT) { g_count[i] = 0; g_cursor[i] = 0; }
}

__global__ void k_hist(const int* __restrict__ nty, const int* __restrict__ dst, int N, int E) {
    __shared__ int c[NT];
    int tid = threadIdx.x;
    int i = blockIdx.x * blockDim.x + tid;
    if (tid < NT) c[tid] = 0;
    __syncthreads();
    if (i < N) atomicAdd(&c[nty[i]], 1);
    if (i < E) atomicAdd(&g_dcnt[dst[i]], 1);
    __syncthreads();
    if (tid < NT && c[tid] > 0) atomicAdd(&g_count[tid], c[tid]);
}

__global__ void k_prefix() {
    int acc = 0;
    for (int t = 0; t < NT; t++) {
        g_offal[t] = acc;
        acc += ((g_count[t] + 127) / 128) * 128;
    }
    g_offal[NT] = acc;
}

__global__ void k_scatter(const int* __restrict__ nty, int N) {
    __shared__ int cnt[NT];
    __shared__ int base[NT];
    int tid = threadIdx.x;
    int i = blockIdx.x * blockDim.x + tid;
    if (tid < NT) cnt[tid] = 0;
    __syncthreads();
    int t = -1, r = 0;
    if (i < N) { t = nty[i]; r = atomicAdd(&cnt[t], 1); }
    __syncthreads();
    if (tid < NT) base[tid] = (cnt[tid] > 0) ? atomicAdd(&g_cursor[tid], cnt[tid]) : 0;
    __syncthreads();
    if (i < N) g_perm[g_offal[t] + base[t] + r] = i;
}

__global__ void k_transpose(const float* __restrict__ WQ, const float* __restrict__ WK,
                            const float* __restrict__ WV) {
    int i = blockIdx.x * blockDim.x + threadIdx.x;
    if (i < 3 * NT * HD * HD) {
        int m = i >> 14;
        int r = i & 16383;
        int j = r >> 7;
        int k = r & 127;
        const float* W = ((m < NT) ? WQ : (m < 2 * NT) ? WK : WV) + (size_t)(m & (NT - 1)) * HD * HD;
        g_WT[(size_t)m * HD * HD + j * HD + k] = W[k * HD + j];
    }
}

__global__ void k_scan_block(int N) {
    __shared__ int sh[256];
    int i = blockIdx.x * 256 + threadIdx.x;
    int v = (i < N) ? g_dcnt[i] : 0;
    sh[threadIdx.x] = v; __syncthreads();
    for (int o = 1; o < 256; o <<= 1) {
        int t = (threadIdx.x >= o) ? sh[threadIdx.x - o] : 0;
        __syncthreads(); sh[threadIdx.x] += t; __syncthreads();
    }
    if (i < N) g_epos[i] = sh[threadIdx.x] - v;
    if (threadIdx.x == 255) g_bsum[blockIdx.x] = sh[255];
}
__global__ void k_scan_top(int nb, int E, int N) {
    __shared__ int sh[256];
    int v = (threadIdx.x < nb) ? g_bsum[threadIdx.x] : 0;
    sh[threadIdx.x] = v; __syncthreads();
    for (int o = 1; o < 256; o <<= 1) {
        int t = (threadIdx.x >= o) ? sh[threadIdx.x - o] : 0;
        __syncthreads(); sh[threadIdx.x] += t; __syncthreads();
    }
    if (threadIdx.x < nb) g_boff[threadIdx.x] = sh[threadIdx.x] - v;
    if (threadIdx.x == 0) g_epos[N] = E;
}
__global__ void k_scan_add(int N) {
    int i = blockIdx.x * 256 + threadIdx.x;
    if (i < N) g_epos[i] += g_boff[blockIdx.x];
}
__global__ void k_escatter(const int* __restrict__ src, const int* __restrict__ dst,
                           const int* __restrict__ ety, int E) {
    int e = blockIdx.x * blockDim.x + threadIdx.x;
    if (e < E) {
        int d = dst[e];
        int p = atomicAdd(&g_dcur[d], 1);
        g_csr[g_epos[d] + p] = make_int2(src[e], ety[e]);
    }
}

// ================= tf32 QKV GEMM (K-chunked, reg-prefetch pipelined; R12-proven) ======
__device__ __forceinline__ void gemm_chunk_tf32(
    const uint32_t* As, const uint32_t* Bs, float acc[4][4][4],
    int mw, int nw, int g, int t4)
{
    #pragma unroll
    for (int k0 = 0; k0 < KCH; k0 += 8) {
        uint32_t af[4][4];
        #pragma unroll
        for (int mi = 0; mi < 4; mi++) {
            int row = mw * 64 + mi * 16;
            af[mi][0] = As[(row + g) * SAC + k0 + t4];
            af[mi][1] = As[(row + g + 8) * SAC + k0 + t4];
            af[mi][2] = As[(row + g) * SAC + k0 + t4 + 4];
            af[mi][3] = As[(row + g + 8) * SAC + k0 + t4 + 4];
        }
        uint32_t bf[4][2];
        #pragma unroll
        for (int ni = 0; ni < 4; ni++) {
            int col = nw * 32 + ni * 8;
            bf[ni][0] = Bs[(col + g) * SAC + k0 + t4];
            bf[ni][1] = Bs[(col + g) * SAC + k0 + t4 + 4];
        }
        #pragma unroll
        for (int mi = 0; mi < 4; mi++)
            #pragma unroll
            for (int ni = 0; ni < 4; ni++)
                mma_tf32(acc[mi][ni], af[mi], bf[ni]);
    }
}

__device__ __forceinline__ void store_chunk_tf32(uint32_t* As, uint32_t* Bs,
                                                 const float4* pa, const float4* pb, int tid) {
    #pragma unroll
    for (int i = 0; i < 4; i++) {
        int idx = tid + i * 256;
        int r = idx >> 3, q = idx & 7;
        float4 v = pa[i];
        *(uint4*)&As[r * SAC + q * 4] = make_uint4(f2tf32(v.x), f2tf32(v.y), f2tf32(v.z), f2tf32(v.w));
        float4 b = pb[i];
        *(uint4*)&Bs[r * SAC + q * 4] = make_uint4(f2tf32(b.x), f2tf32(b.y), f2tf32(b.z), f2tf32(b.w));
    }
}

__global__ __launch_bounds__(256) void k_qkv_mma(const float* __restrict__ x, int N) {
    __shared__ uint32_t As[128 * SAC];
    __shared__ uint32_t Bs[128 * SAC];
    __shared__ int rows[128];

    int tid = threadIdx.x;
    int wid = tid >> 5, lane = tid & 31;
    int g = lane >> 2, t4 = lane & 3;
    int mw = wid & 1, nw = wid >> 1;
    int base = blockIdx.x * 128;

    int ty = NT - 1;
    #pragma unroll
    for (int i = 0; i < NT; i++)
        if (base >= g_offal[i] && base < g_offal[i + 1]) ty = i;
    int total = g_offal[NT];
    if (tid < 128) {
        int gi = base + tid;
        rows[tid] = (gi < total) ? g_perm[gi] : -1;
    }
    __syncthreads();

    for (int mat = 0; mat < 3; mat++) {
        const float* Wt = g_WT + (size_t)(mat * NT + ty) * HD * HD;

        float acc[4][4][4];
        #pragma unroll
        for (int mi = 0; mi < 4; mi++)
            #pragma unroll
            for (int ni = 0; ni < 4; ni++)
                #pragma unroll
                for (int r = 0; r < 4; r++) acc[mi][ni][r] = 0.0f;

        float4 pa[4], pb[4];
        #pragma unroll
        for (int i = 0; i < 4; i++) {
            int idx = tid + i * 256;
            int r = idx >> 3, q = idx & 7;
            int node = rows[r];
            pa[i] = (node >= 0) ? *(const float4*)(x + (size_t)node * HD + q * 4)
                                : make_float4(0.f, 0.f, 0.f, 0.f);
            pb[i] = *(const float4*)(Wt + (size_t)r * HD + q * 4);
        }

        for (int ch = 0; ch < NCHUNK; ch++) {
            __syncthreads();
            store_chunk_tf32(As, Bs, pa, pb, tid);
            if (ch + 1 < NCHUNK) {
                int k0 = (ch + 1) * KCH;
                #pragma unroll
                for (int i = 0; i < 4; i++) {
                    int idx = tid + i * 256;
                    int r = idx >> 3, q = idx & 7;
                    int node = rows[r];
                    pa[i] = (node >= 0) ? *(const float4*)(x + (size_t)node * HD + k0 + q * 4)
                                        : make_float4(0.f, 0.f, 0.f, 0.f);
                    pb[i] = *(const float4*)(Wt + (size_t)r * HD + k0 + q * 4);
                }
            }
            __syncthreads();
            gemm_chunk_tf32(As, Bs, acc, mw, nw, g, t4);
        }

        #pragma unroll
        for (int mi = 0; mi < 4; mi++) {
            int r0 = mw * 64 + mi * 16 + g;
            int n0 = rows[r0], n1 = rows[r0 + 8];
            #pragma unroll
            for (int ni = 0; ni < 4; ni++) {
                int col = nw * 32 + ni * 8 + t4 * 2;
                if (mat == 1) {
                    if (n0 >= 0) g_Kh[(size_t)n0 * (HD/2) + (col >> 1)] = pack_bf16x2(acc[mi][ni][0], acc[mi][ni][1]);
                    if (n1 >= 0) g_Kh[(size_t)n1 * (HD/2) + (col >> 1)] = pack_bf16x2(acc[mi][ni][2], acc[mi][ni][3]);
                } else {
                    float* Out = (mat == 0) ? g_Q : g_V;
                    if (n0 >= 0) *(float2*)(Out + (size_t)n0 * HD + col) = make_float2(acc[mi][ni][0], acc[mi][ni][1]);
                    if (n1 >= 0) *(float2*)(Out + (size_t)n1 * HD + col) = make_float2(acc[mi][ni][2], acc[mi][ni][3]);
                }
            }
        }
    }
}

// ================= bf16 P GEMM (m16n8k16; score path only, bf16 precision is ample) ====
// Chunk = 128 rows x 32 k's = 16 bf16x2 pairs/row; smem stride SB=20 (conflict-free).
__device__ __forceinline__ void gemm_chunk_bf16(
    const uint32_t* Ap, const uint32_t* Bp, float acc[4][4][4],
    int mw, int nw, int g, int t4)
{
    #pragma unroll
    for (int kp0 = 0; kp0 < 16; kp0 += 8) {      // two k-steps of 16 k's (8 pairs)
        uint32_t af[4][4];
        #pragma unroll
        for (int mi = 0; mi < 4; mi++) {
            int row = mw * 64 + mi * 16;
            af[mi][0] = Ap[(row + g) * SB + kp0 + t4];
            af[mi][1] = Ap[(row + g + 8) * SB + kp0 + t4];
            af[mi][2] = Ap[(row + g) * SB + kp0 + t4 + 4];
            af[mi][3] = Ap[(row + g + 8) * SB + kp0 + t4 + 4];
        }
        uint32_t bf[4][2];
        #pragma unroll
        for (int ni = 0; ni < 4; ni++) {
            int col = nw * 32 + ni * 8;
            bf[ni][0] = Bp[(col + g) * SB + kp0 + t4];
            bf[ni][1] = Bp[(col + g) * SB + kp0 + t4 + 4];
        }
        #pragma unroll
        for (int mi = 0; mi < 4; mi++)
            #pragma unroll
            for (int ni = 0; ni < 4; ni++)
                mma_bf16(acc[mi][ni], af[mi], bf[ni]);
    }
}

__device__ __forceinline__ void store_chunk_bf16(uint32_t* Ap, uint32_t* Bp,
                                                 const float4* pa, const float4* pb, int tid) {
    #pragma unroll
    for (int i = 0; i < 4; i++) {
        int idx = tid + i * 256;
        int r = idx >> 3, q = idx & 7;           // q indexes float4 within 32-float chunk row
        float4 v = pa[i];
        Ap[r * SB + q * 2]     = pack_bf16x2(v.x, v.y);
        Ap[r * SB + q * 2 + 1] = pack_bf16x2(v.z, v.w);
        float4 b = pb[i];
        Bp[r * SB + q * 2]     = pack_bf16x2(b.x, b.y);
        Bp[r * SB + q * 2 + 1] = pack_bf16x2(b.z, b.w);
    }
}

__global__ __launch_bounds__(256) void k_p_mma(const float* __restrict__ We, int N) {
    __shared__ uint32_t Ap[128 * SB];
    __shared__ uint32_t Bp[128 * SB];

    int tid = threadIdx.x;
    int wid = tid >> 5, lane = tid & 31;
    int g = lane >> 2, t4 = lane & 3;
    int mw = wid & 1, nw = wid >> 1;
    int base = blockIdx.x * 128;

    for (int t = 0; t < ET; t++) {
        const float* Wt = We + (size_t)t * HD * HD;

        float acc[4][4][4];
        #pragma unroll
        for (int mi = 0; mi < 4; mi++)
            #pragma unroll
            for (int ni = 0; ni < 4; ni++)
                #pragma unroll
                for (int r = 0; r < 4; r++) acc[mi][ni][r] = 0.0f;

        float4 pa[4], pb[4];
        #pragma unroll
        for (int i = 0; i < 4; i++) {
            int idx = tid + i * 256;
            int r = idx >> 3, q = idx & 7;
            int node = base + r;
            pa[i] = (node < N) ? *(const float4*)(g_Q + (size_t)node * HD + q * 4)
                               : make_float4(0.f, 0.f, 0.f, 0.f);
            pb[i] = *(const float4*)(Wt + (size_t)r * HD + q * 4);
        }

        for (int ch = 0; ch < NCHUNK; ch++) {
            __syncthreads();
            store_chunk_bf16(Ap, Bp, pa, pb, tid);
            if (ch + 1 < NCHUNK) {
                int k0 = (ch + 1) * KCH;
                #pragma unroll
                for (int i = 0; i < 4; i++) {
                    int idx = tid + i * 256;
                    int r = idx >> 3, q = idx & 7;
                    int node = base + r;
                    pa[i] = (node < N) ? *(const float4*)(g_Q + (size_t)node * HD + k0 + q * 4)
                                       : make_float4(0.f, 0.f, 0.f, 0.f);
                    pb[i] = *(const float4*)(Wt + (size_t)r * HD + k0 + q * 4);
                }
            }
            __syncthreads();
            gemm_chunk_bf16(Ap, Bp, acc, mw, nw, g, t4);
        }

        #pragma unroll
        for (int mi = 0; mi < 4; mi++) {
            int r0 = mw * 64 + mi * 16 + g;
            int node0 = base + r0, node1 = base + r0 + 8;
            #pragma unroll
            for (int ni = 0; ni < 4; ni++) {
                int col = nw * 32 + ni * 8 + t4 * 2;
                if (node0 < N) g_Ph[((size_t)node0 * ET + t) * (HD/2) + (col >> 1)] = pack_bf16x2(acc[mi][ni][0], acc[mi][ni][1]);
                if (node1 < N) g_Ph[((size_t)node1 * ET + t) * (HD/2) + (col >> 1)] = pack_bf16x2(acc[mi][ni][2], acc[mi][ni][3]);
            }
        }
    }
}

// ================= fused single-pass edge kernel (x4 unrolled; R12-proven) ============
__global__ __launch_bounds__(256) void k_edge(const float* __restrict__ mu,
                                              float* __restrict__ out, int N) {
    __shared__ float Psh[8][ET][HD];   // 32KB

    int wid = threadIdx.x >> 5;
    int l = threadIdx.x & 31;
    int n = blockIdx.x * 8 + wid;
    if (n >= N) return;

    const float SCALE = 0.08838834764831845f;  // 1/sqrt(128)

    #pragma unroll
    for (int t = 0; t < ET; t++) {
        float m = mu[t] * SCALE;
        uint2 u = *(const uint2*)(g_Ph + ((size_t)n * ET + t) * (HD/2) + l * 2);
        float2 p0 = bf2f(u.x), p1 = bf2f(u.y);
        Psh[wid][t][l*4 + 0] = p0.x * m;
        Psh[wid][t][l*4 + 1] = p0.y * m;
        Psh[wid][t][l*4 + 2] = p1.x * m;
        Psh[wid][t][l*4 + 3] = p1.y * m;
    }
    __syncwarp();

    int s0 = g_epos[n], s1 = g_epos[n + 1];

    float sum = 0.0f;
    float4 acc = make_float4(0.f, 0.f, 0.f, 0.f);
    int i = s0;

    for (; i + 3 < s1; i += 4) {
        int2 e0 = g_csr[i];
        int2 e1 = g_csr[i + 1];
        int2 e2 = g_csr[i + 2];
        int2 e3 = g_csr[i + 3];
        uint2 u0 = *(const uint2*)(g_Kh + (size_t)e0.x * (HD/2) + l * 2);
        uint2 u1 = *(const uint2*)(g_Kh + (size_t)e1.x * (HD/2) + l * 2);
        uint2 u2 = *(const uint2*)(g_Kh + (size_t)e2.x * (HD/2) + l * 2);
        uint2 u3 = *(const uint2*)(g_Kh + (size_t)e3.x * (HD/2) + l * 2);
        float4 w0 = *((const float4*)(g_V + (size_t)e0.x * HD) + l);
        float4 w1 = *((const float4*)(g_V + (size_t)e1.x * HD) + l);
        float4 w2 = *((const float4*)(g_V + (size_t)e2.x * HD) + l);
        float4 w3 = *((const float4*)(g_V + (size_t)e3.x * HD) + l);

        float2 a00 = bf2f(u0.x), a01 = bf2f(u0.y);
        float2 a10 = bf2f(u1.x), a11 = bf2f(u1.y);
        float2 a20 = bf2f(u2.x), a21 = bf2f(u2.y);
        float2 a30 = bf2f(u3.x), a31 = bf2f(u3.y);
        const float* p0 = &Psh[wid][e0.y][l*4];
        const float* p1 = &Psh[wid][e1.y][l*4];
        const float* p2 = &Psh[wid][e2.y][l*4];
        const float* p3 = &Psh[wid][e3.y][l*4];
        float v0 = a00.x * p0[0] + a00.y * p0[1] + a01.x * p0[2] + a01.y * p0[3];
        float v1 = a10.x * p1[0] + a10.y * p1[1] + a11.x * p1[2] + a11.y * p1[3];
        float v2 = a20.x * p2[0] + a20.y * p2[1] + a21.x * p2[2] + a21.y * p2[3];
        float v3 = a30.x * p3[0] + a30.y * p3[1] + a31.x * p3[2] + a31.y * p3[3];
        #pragma unroll
        for (int o = 16; o > 0; o >>= 1) {
            v0 += __shfl_xor_sync(0xffffffffu, v0, o);
            v1 += __shfl_xor_sync(0xffffffffu, v1, o);
            v2 += __shfl_xor_sync(0xffffffffu, v2, o);
            v3 += __shfl_xor_sync(0xffffffffu, v3, o);
        }
        float ex0 = __expf(v0);
        float ex1 = __expf(v1);
        float ex2 = __expf(v2);
        float ex3 = __expf(v3);
        sum += (ex0 + ex1) + (ex2 + ex3);
        acc.x += ex0 * w0.x + ex1 * w1.x + ex2 * w2.x + ex3 * w3.x;
        acc.y += ex0 * w0.y + ex1 * w1.y + ex2 * w2.y + ex3 * w3.y;
        acc.z += ex0 * w0.z + ex1 * w1.z + ex2 * w2.z + ex3 * w3.z;
        acc.w += ex0 * w0.w + ex1 * w1.w + ex2 * w2.w + ex3 * w3.w;
    }
    for (; i < s1; i++) {
        int2 e = g_csr[i];
        uint2 u = *(const uint2*)(g_Kh + (size_t)e.x * (HD/2) + l * 2);
        float4 vv = *((const float4*)(g_V + (size_t)e.x * HD) + l);
        float2 k0 = bf2f(u.x), k1 = bf2f(u.y);
        const float* p = &Psh[wid][e.y][l*4];
        float v = k0.x * p[0] + k0.y * p[1] + k1.x * p[2] + k1.y * p[3];
        #pragma unroll
        for (int o = 16; o > 0; o >>= 1) v += __shfl_xor_sync(0xffffffffu, v, o);
        float ex = __expf(v);
        sum += ex;
        acc.x += ex * vv.x; acc.y += ex * vv.y; acc.z += ex * vv.z; acc.w += ex * vv.w;
    }
    float inv = 1.0f / (sum + 1e-10f);
    acc.x *= inv; acc.y *= inv; acc.z *= inv; acc.w *= inv;
    *((float4*)(out + (size_t)n * HD) + l) = acc;
}

extern "C" void kernel_launch(void* const* d_in, const int* in_sizes, int n_in,
                              void* d_out, int out_size) {
    const float* x   = (const float*)d_in[0];
    const int*   ei  = (const int*)  d_in[1];
    const int*   ety = (const int*)  d_in[2];
    const int*   nty = (const int*)  d_in[3];
    const float* WQ  = (const float*)d_in[4];
    const float* WK  = (const float*)d_in[5];
    const float* WV  = (const float*)d_in[6];
    const float* We  = (const float*)d_in[7];
    const float* mu  = (const float*)d_in[8];
    float* out = (float*)d_out;

    int N = in_sizes[3];
    int E = in_sizes[2];
    const int* src = ei;
    const int* dst = ei + E;

    int nb = (N + 255) / 256;

    k_init<<<(N + NT * 128 + 255) / 256, 256>>>(N);
    k_hist<<<(E + 255) / 256, 256>>>(nty, dst, N, E);
    k_prefix<<<1, 1>>>();
    k_scatter<<<(N + 255) / 256, 256>>>(nty, N);
    k_transpose<<<(3 * NT * HD * HD + 255) / 256, 256>>>(WQ, WK, WV);

    k_scan_block<<<nb, 256>>>(N);
    k_scan_top<<<1, 256>>>(nb, E, N);
    k_scan_add<<<nb, 256>>>(N);
    k_escatter<<<(E + 255) / 256, 256>>>(src, dst, ety, E);

    k_qkv_mma<<<(N + 127) / 128 + NT, 256>>>(x, N);
    k_p_mma<<<(N + 127) / 128, 256>>>(We, N);

    k_edge<<<(N + 7) / 8, 256>>>(mu, out, N);
}

// round 16
// speedup vs baseline: 1.2222x; 1.0739x over previous
#include <cuda_runtime.h>
#include <cstdint>

#define HD 128
#define NT 4
#define ET 8
#define N_MAX 50000
#define E_MAX 800000
#define NPAD_MAX (N_MAX + NT*128 + 256)

// ---- scratch (__device__ globals) ----
__device__ uint32_t g_Qh[N_MAX*HD/2];                 // bf16x2 pairs (score path)
__device__ uint32_t g_Kh[N_MAX*HD/2];                 // bf16x2 pairs (score path)
__device__ float    g_V[N_MAX*HD];                    // fp32 (output path)
__device__ uint32_t g_Ph[(size_t)N_MAX*ET*HD/2];      // bf16x2, layout [n][t][k]
__device__ float    g_WT[3*NT*HD*HD];                 // W_Q/K/V transposed
__device__ int      g_perm[NPAD_MAX];
__device__ int      g_count[NT];
__device__ int      g_cursor[NT];
__device__ int      g_offal[NT+1];
// CSR over dst: (src, ety) pairs
__device__ int      g_dcnt[N_MAX];
__device__ int      g_dcur[N_MAX];
__device__ int      g_epos[N_MAX+1];
__device__ int2     g_csr[E_MAX];
__device__ int      g_bsum[256];
__device__ int      g_boff[256];

// ================= helpers =================
__device__ __forceinline__ uint32_t f2tf32(float f) {
    uint32_t r; asm("cvt.rna.tf32.f32 %0, %1;" : "=r"(r) : "f"(f)); return r;
}
__device__ __forceinline__ void mma_tf32(float* d, const uint32_t* a, const uint32_t* b) {
    asm volatile("mma.sync.aligned.m16n8k8.row.col.f32.tf32.tf32.f32 "
        "{%0,%1,%2,%3}, {%4,%5,%6,%7}, {%8,%9}, {%0,%1,%2,%3};"
        : "+f"(d[0]), "+f"(d[1]), "+f"(d[2]), "+f"(d[3])
        : "r"(a[0]), "r"(a[1]), "r"(a[2]), "r"(a[3]), "r"(b[0]), "r"(b[1]));
}
__device__ __forceinline__ void mma_bf16(float* d, const uint32_t* a, const uint32_t* b) {
    asm volatile("mma.sync.aligned.m16n8k16.row.col.f32.bf16.bf16.f32 "
        "{%0,%1,%2,%3}, {%4,%5,%6,%7}, {%8,%9}, {%0,%1,%2,%3};"
        : "+f"(d[0]), "+f"(d[1]), "+f"(d[2]), "+f"(d[3])
        : "r"(a[0]), "r"(a[1]), "r"(a[2]), "r"(a[3]), "r"(b[0]), "r"(b[1]));
}
__device__ __forceinline__ uint32_t pack_bf16x2(float a, float b) {
    uint32_t r; asm("cvt.rn.bf16x2.f32 %0, %1, %2;" : "=r"(r) : "f"(b), "f"(a)); return r;
}
__device__ __forceinline__ float2 bf2f(uint32_t u) {
    float2 r;
    r.x = __uint_as_float(u << 16);
    r.y = __uint_as_float(u & 0xFFFF0000u);
    return r;
}

// tf32 tiles: 128 rows x 32 k-cols, stride 36 (banks (4g+t4): conflict-free)
#define SAC 36
#define KCH 32
#define NCHUNK (HD / KCH)
// bf16 tiles: 128 rows x 16 bf16x2 pairs per chunk, stride 20 (banks (20g+t4): conflict-free)
#define SB 20

// ================= setup kernels =================
__global__ void k_init(int N) {
    int i = blockIdx.x * blockDim.x + threadIdx.x;
    if (i < N) { g_dcnt[i] = 0; g_dcur[i] = 0; }
    if (i < N + NT * 128) g_perm[i] = -1;
    if (i < NT) { g_count[i] = 0; g_cursor[i] = 0; }
}

__global__ void k_hist(const int* __restrict__ nty, const int* __restrict__ dst, int N, int E) {
    __shared__ int c[NT];
    int tid = threadIdx.x;
    int i = blockIdx.x * blockDim.x + tid;
    if (tid < NT) c[tid] = 0;
    __syncthreads();
    if (i < N) atomicAdd(&c[nty[i]], 1);
    if (i < E) atomicAdd(&g_dcnt[dst[i]], 1);
    __syncthreads();
    if (tid < NT && c[tid] > 0) atomicAdd(&g_count[tid], c[tid]);
}

__global__ void k_prefix() {
    int acc = 0;
    for (int t = 0; t < NT; t++) {
        g_offal[t] = acc;
        acc += ((g_count[t] + 127) / 128) * 128;
    }
    g_offal[NT] = acc;
}

__global__ void k_scatter(const int* __restrict__ nty, int N) {
    __shared__ int cnt[NT];
    __shared__ int base[NT];
    int tid = threadIdx.x;
    int i = blockIdx.x * blockDim.x + tid;
    if (tid < NT) cnt[tid] = 0;
    __syncthreads();
    int t = -1, r = 0;
    if (i < N) { t = nty[i]; r = atomicAdd(&cnt[t], 1); }
    __syncthreads();
    if (tid < NT) base[tid] = (cnt[tid] > 0) ? atomicAdd(&g_cursor[tid], cnt[tid]) : 0;
    __syncthreads();
    if (i < N) g_perm[g_offal[t] + base[t] + r] = i;
}

__global__ void k_transpose(const float* __restrict__ WQ, const float* __restrict__ WK,
                            const float* __restrict__ WV) {
    int i = blockIdx.x * blockDim.x + threadIdx.x;
    if (i < 3 * NT * HD * HD) {
        int m = i >> 14;
        int r = i & 16383;
        int j = r >> 7;
        int k = r & 127;
        const float* W = ((m < NT) ? WQ : (m < 2 * NT) ? WK : WV) + (size_t)(m & (NT - 1)) * HD * HD;
        g_WT[(size_t)m * HD * HD + j * HD + k] = W[k * HD + j];
    }
}

__global__ void k_scan_block(int N) {
    __shared__ int sh[256];
    int i = blockIdx.x * 256 + threadIdx.x;
    int v = (i < N) ? g_dcnt[i] : 0;
    sh[threadIdx.x] = v; __syncthreads();
    for (int o = 1; o < 256; o <<= 1) {
        int t = (threadIdx.x >= o) ? sh[threadIdx.x - o] : 0;
        __syncthreads(); sh[threadIdx.x] += t; __syncthreads();
    }
    if (i < N) g_epos[i] = sh[threadIdx.x] - v;
    if (threadIdx.x == 255) g_bsum[blockIdx.x] = sh[255];
}
__global__ void k_scan_top(int nb, int E, int N) {
    __shared__ int sh[256];
    int v = (threadIdx.x < nb) ? g_bsum[threadIdx.x] : 0;
    sh[threadIdx.x] = v; __syncthreads();
    for (int o = 1; o < 256; o <<= 1) {
        int t = (threadIdx.x >= o) ? sh[threadIdx.x - o] : 0;
        __syncthreads(); sh[threadIdx.x] += t; __syncthreads();
    }
    if (threadIdx.x < nb) g_boff[threadIdx.x] = sh[threadIdx.x] - v;
    if (threadIdx.x == 0) g_epos[N] = E;
}
__global__ void k_scan_add(int N) {
    int i = blockIdx.x * 256 + threadIdx.x;
    if (i < N) g_epos[i] += g_boff[blockIdx.x];
}
__global__ void k_escatter(const int* __restrict__ src, const int* __restrict__ dst,
                           const int* __restrict__ ety, int E) {
    int e = blockIdx.x * blockDim.x + threadIdx.x;
    if (e < E) {
        int d = dst[e];
        int p = atomicAdd(&g_dcur[d], 1);
        g_csr[g_epos[d] + p] = make_int2(src[e], ety[e]);
    }
}

// ================= MMA chunk primitives =================
__device__ __forceinline__ void gemm_chunk_tf32(
    const uint32_t* As, const uint32_t* Bs, float acc[4][4][4],
    int mw, int nw, int g, int t4)
{
    #pragma unroll
    for (int k0 = 0; k0 < KCH; k0 += 8) {
        uint32_t af[4][4];
        #pragma unroll
        for (int mi = 0; mi < 4; mi++) {
            int row = mw * 64 + mi * 16;
            af[mi][0] = As[(row + g) * SAC + k0 + t4];
            af[mi][1] = As[(row + g + 8) * SAC + k0 + t4];
            af[mi][2] = As[(row + g) * SAC + k0 + t4 + 4];
            af[mi][3] = As[(row + g + 8) * SAC + k0 + t4 + 4];
        }
        uint32_t bf[4][2];
        #pragma unroll
        for (int ni = 0; ni < 4; ni++) {
            int col = nw * 32 + ni * 8;
            bf[ni][0] = Bs[(col + g) * SAC + k0 + t4];
            bf[ni][1] = Bs[(col + g) * SAC + k0 + t4 + 4];
        }
        #pragma unroll
        for (int mi = 0; mi < 4; mi++)
            #pragma unroll
            for (int ni = 0; ni < 4; ni++)
                mma_tf32(acc[mi][ni], af[mi], bf[ni]);
    }
}

__device__ __forceinline__ void gemm_chunk_bf16(
    const uint32_t* Ap, const uint32_t* Bp, float acc[4][4][4],
    int mw, int nw, int g, int t4)
{
    #pragma unroll
    for (int kp0 = 0; kp0 < 16; kp0 += 8) {
        uint32_t af[4][4];
        #pragma unroll
        for (int mi = 0; mi < 4; mi++) {
            int row = mw * 64 + mi * 16;
            af[mi][0] = Ap[(row + g) * SB + kp0 + t4];
            af[mi][1] = Ap[(row + g + 8) * SB + kp0 + t4];
            af[mi][2] = Ap[(row + g) * SB + kp0 + t4 + 4];
            af[mi][3] = Ap[(row + g + 8) * SB + kp0 + t4 + 4];
        }
        uint32_t bf[4][2];
        #pragma unroll
        for (int ni = 0; ni < 4; ni++) {
            int col = nw * 32 + ni * 8;
            bf[ni][0] = Bp[(col + g) * SB + kp0 + t4];
            bf[ni][1] = Bp[(col + g) * SB + kp0 + t4 + 4];
        }
        #pragma unroll
        for (int mi = 0; mi < 4; mi++)
            #pragma unroll
            for (int ni = 0; ni < 4; ni++)
                mma_bf16(acc[mi][ni], af[mi], bf[ni]);
    }
}

// ================= QKV GEMM: Q,K via bf16 MMA; V via tf32 =================
__global__ __launch_bounds__(256) void k_qkv_mma(const float* __restrict__ x, int N) {
    __shared__ uint32_t As[128 * SAC];   // reused by both pipelines (bf16 uses SB stride)
    __shared__ uint32_t Bs[128 * SAC];
    __shared__ int rows[128];

    int tid = threadIdx.x;
    int wid = tid >> 5, lane = tid & 31;
    int g = lane >> 2, t4 = lane & 3;
    int mw = wid & 1, nw = wid >> 1;
    int base = blockIdx.x * 128;

    int ty = NT - 1;
    #pragma unroll
    for (int i = 0; i < NT; i++)
        if (base >= g_offal[i] && base < g_offal[i + 1]) ty = i;
    int total = g_offal[NT];
    if (tid < 128) {
        int gi = base + tid;
        rows[tid] = (gi < total) ? g_perm[gi] : -1;
    }
    __syncthreads();

    // ---- Q and K: bf16 pipeline ----
    for (int mat = 0; mat < 2; mat++) {
        const float* Wt = g_WT + (size_t)(mat * NT + ty) * HD * HD;
        uint32_t* Out = (mat == 0) ? g_Qh : g_Kh;

        float acc[4][4][4];
        #pragma unroll
        for (int mi = 0; mi < 4; mi++)
            #pragma unroll
            for (int ni = 0; ni < 4; ni++)
                #pragma unroll
                for (int r = 0; r < 4; r++) acc[mi][ni][r] = 0.0f;

        float4 pa[4], pb[4];
        #pragma unroll
        for (int i = 0; i < 4; i++) {
            int idx = tid + i * 256;
            int r = idx >> 3, q = idx & 7;
            int node = rows[r];
            pa[i] = (node >= 0) ? *(const float4*)(x + (size_t)node * HD + q * 4)
                                : make_float4(0.f, 0.f, 0.f, 0.f);
            pb[i] = *(const float4*)(Wt + (size_t)r * HD + q * 4);
        }

        for (int ch = 0; ch < NCHUNK; ch++) {
            __syncthreads();
            #pragma unroll
            for (int i = 0; i < 4; i++) {
                int idx = tid + i * 256;
                int r = idx >> 3, q = idx & 7;
                As[r * SB + q * 2]     = pack_bf16x2(pa[i].x, pa[i].y);
                As[r * SB + q * 2 + 1] = pack_bf16x2(pa[i].z, pa[i].w);
                Bs[r * SB + q * 2]     = pack_bf16x2(pb[i].x, pb[i].y);
                Bs[r * SB + q * 2 + 1] = pack_bf16x2(pb[i].z, pb[i].w);
            }
            if (ch + 1 < NCHUNK) {
                int k0 = (ch + 1) * KCH;
                #pragma unroll
                for (int i = 0; i < 4; i++) {
                    int idx = tid + i * 256;
                    int r = idx >> 3, q = idx & 7;
                    int node = rows[r];
                    pa[i] = (node >= 0) ? *(const float4*)(x + (size_t)node * HD + k0 + q * 4)
                                        : make_float4(0.f, 0.f, 0.f, 0.f);
                    pb[i] = *(const float4*)(Wt + (size_t)r * HD + k0 + q * 4);
                }
            }
            __syncthreads();
            gemm_chunk_bf16(As, Bs, acc, mw, nw, g, t4);
        }

        #pragma unroll
        for (int mi = 0; mi < 4; mi++) {
            int r0 = mw * 64 + mi * 16 + g;
            int n0 = rows[r0], n1 = rows[r0 + 8];
            #pragma unroll
            for (int ni = 0; ni < 4; ni++) {
                int col = nw * 32 + ni * 8 + t4 * 2;
                if (n0 >= 0) Out[(size_t)n0 * (HD/2) + (col >> 1)] = pack_bf16x2(acc[mi][ni][0], acc[mi][ni][1]);
                if (n1 >= 0) Out[(size_t)n1 * (HD/2) + (col >> 1)] = pack_bf16x2(acc[mi][ni][2], acc[mi][ni][3]);
            }
        }
    }

    // ---- V: tf32 pipeline (output precision path) ----
    {
        const float* Wt = g_WT + (size_t)(2 * NT + ty) * HD * HD;

        float acc[4][4][4];
        #pragma unroll
        for (int mi = 0; mi < 4; mi++)
            #pragma unroll
            for (int ni = 0; ni < 4; ni++)
                #pragma unroll
                for (int r = 0; r < 4; r++) acc[mi][ni][r] = 0.0f;

        float4 pa[4], pb[4];
        #pragma unroll
        for (int i = 0; i < 4; i++) {
            int idx = tid + i * 256;
            int r = idx >> 3, q = idx & 7;
            int node = rows[r];
            pa[i] = (node >= 0) ? *(const float4*)(x + (size_t)node * HD + q * 4)
                                : make_float4(0.f, 0.f, 0.f, 0.f);
            pb[i] = *(const float4*)(Wt + (size_t)r * HD + q * 4);
        }

        for (int ch = 0; ch < NCHUNK; ch++) {
            __syncthreads();
            #pragma unroll
            for (int i = 0; i < 4; i++) {
                int idx = tid + i * 256;
                int r = idx >> 3, q = idx & 7;
                *(uint4*)&As[r * SAC + q * 4] = make_uint4(f2tf32(pa[i].x), f2tf32(pa[i].y), f2tf32(pa[i].z), f2tf32(pa[i].w));
                *(uint4*)&Bs[r * SAC + q * 4] = make_uint4(f2tf32(pb[i].x), f2tf32(pb[i].y), f2tf32(pb[i].z), f2tf32(pb[i].w));
            }
            if (ch + 1 < NCHUNK) {
                int k0 = (ch + 1) * KCH;
                #pragma unroll
                for (int i = 0; i < 4; i++) {
                    int idx = tid + i * 256;
                    int r = idx >> 3, q = idx & 7;
                    int node = rows[r];
                    pa[i] = (node >= 0) ? *(const float4*)(x + (size_t)node * HD + k0 + q * 4)
                                        : make_float4(0.f, 0.f, 0.f, 0.f);
                    pb[i] = *(const float4*)(Wt + (size_t)r * HD + k0 + q * 4);
                }
            }
            __syncthreads();
            gemm_chunk_tf32(As, Bs, acc, mw, nw, g, t4);
        }

        #pragma unroll
        for (int mi = 0; mi < 4; mi++) {
            int r0 = mw * 64 + mi * 16 + g;
            int n0 = rows[r0], n1 = rows[r0 + 8];
            #pragma unroll
            for (int ni = 0; ni < 4; ni++) {
                int col = nw * 32 + ni * 8 + t4 * 2;
                if (n0 >= 0) *(float2*)(g_V + (size_t)n0 * HD + col) = make_float2(acc[mi][ni][0], acc[mi][ni][1]);
                if (n1 >= 0) *(float2*)(g_V + (size_t)n1 * HD + col) = make_float2(acc[mi][ni][2], acc[mi][ni][3]);
            }
        }
    }
}

// ================= bf16 P GEMM: A = g_Qh (direct bf16 copy), B = We (cvt) =============
__global__ __launch_bounds__(256) void k_p_mma(const float* __restrict__ We, int N) {
    __shared__ uint32_t Ap[128 * SB];
    __shared__ uint32_t Bp[128 * SB];

    int tid = threadIdx.x;
    int wid = tid >> 5, lane = tid & 31;
    int g = lane >> 2, t4 = lane & 3;
    int mw = wid & 1, nw = wid >> 1;
    int base = blockIdx.x * 128;

    for (int t = 0; t < ET; t++) {
        const float* Wt = We + (size_t)t * HD * HD;

        float acc[4][4][4];
        #pragma unroll
        for (int mi = 0; mi < 4; mi++)
            #pragma unroll
            for (int ni = 0; ni < 4; ni++)
                #pragma unroll
                for (int r = 0; r < 4; r++) acc[mi][ni][r] = 0.0f;

        uint4 qa[2];
        float4 pb[4];
        // prefetch chunk 0: A = 128 rows x 16 u32 (bf16x2) = 512 uint4, 2/thread
        #pragma unroll
        for (int i = 0; i < 2; i++) {
            int idx = tid + i * 256;
            int r = idx >> 2, q = idx & 3;
            int node = base + r;
            qa[i] = (node < N) ? *(const uint4*)(g_Qh + (size_t)node * (HD/2) + q * 4)
                               : make_uint4(0, 0, 0, 0);
        }
        #pragma unroll
        for (int i = 0; i < 4; i++) {
            int idx = tid + i * 256;
            int r = idx >> 3, q = idx & 7;
            pb[i] = *(const float4*)(Wt + (size_t)r * HD + q * 4);
        }

        for (int ch = 0; ch < NCHUNK; ch++) {
            __syncthreads();
            #pragma unroll
            for (int i = 0; i < 2; i++) {
                int idx = tid + i * 256;
                int r = idx >> 2, q = idx & 3;
                *(uint4*)&Ap[r * SB + q * 4] = qa[i];
            }
            #pragma unroll
            for (int i = 0; i < 4; i++) {
                int idx = tid + i * 256;
                int r = idx >> 3, q = idx & 7;
                Bp[r * SB + q * 2]     = pack_bf16x2(pb[i].x, pb[i].y);
                Bp[r * SB + q * 2 + 1] = pack_bf16x2(pb[i].z, pb[i].w);
            }
            if (ch + 1 < NCHUNK) {
                int kp = (ch + 1) * (KCH / 2);   // u32-pair offset into Q row
                int k0 = (ch + 1) * KCH;
                #pragma unroll
                for (int i = 0; i < 2; i++) {
                    int idx = tid + i * 256;
                    int r = idx >> 2, q = idx & 3;
                    int node = base + r;
                    qa[i] = (node < N) ? *(const uint4*)(g_Qh + (size_t)node * (HD/2) + kp + q * 4)
                                       : make_uint4(0, 0, 0, 0);
                }
                #pragma unroll
                for (int i = 0; i < 4; i++) {
                    int idx = tid + i * 256;
                    int r = idx >> 3, q = idx & 7;
                    pb[i] = *(const float4*)(Wt + (size_t)r * HD + k0 + q * 4);
                }
            }
            __syncthreads();
            gemm_chunk_bf16(Ap, Bp, acc, mw, nw, g, t4);
        }

        #pragma unroll
        for (int mi = 0; mi < 4; mi++) {
            int r0 = mw * 64 + mi * 16 + g;
            int node0 = base + r0, node1 = base + r0 + 8;
            #pragma unroll
            for (int ni = 0; ni < 4; ni++) {
                int col = nw * 32 + ni * 8 + t4 * 2;
                if (node0 < N) g_Ph[((size_t)node0 * ET + t) * (HD/2) + (col >> 1)] = pack_bf16x2(acc[mi][ni][0], acc[mi][ni][1]);
                if (node1 < N) g_Ph[((size_t)node1 * ET + t) * (HD/2) + (col >> 1)] = pack_bf16x2(acc[mi][ni][2], acc[mi][ni][3]);
            }
        }
    }
}

// ================= fused single-pass edge kernel (x4 unrolled; R12/R14-proven) ========
__global__ __launch_bounds__(256) void k_edge(const float* __restrict__ mu,
                                              float* __restrict__ out, int N) {
    __shared__ float Psh[8][ET][HD];   // 32KB

    int wid = threadIdx.x >> 5;
    int l = threadIdx.x & 31;
    int n = blockIdx.x * 8 + wid;
    if (n >= N) return;

    const float SCALE = 0.08838834764831845f;  // 1/sqrt(128)

    #pragma unroll
    for (int t = 0; t < ET; t++) {
        float m = mu[t] * SCALE;
        uint2 u = *(const uint2*)(g_Ph + ((size_t)n * ET + t) * (HD/2) + l * 2);
        float2 p0 = bf2f(u.x), p1 = bf2f(u.y);
        Psh[wid][t][l*4 + 0] = p0.x * m;
        Psh[wid][t][l*4 + 1] = p0.y * m;
        Psh[wid][t][l*4 + 2] = p1.x * m;
        Psh[wid][t][l*4 + 3] = p1.y * m;
    }
    __syncwarp();

    int s0 = g_epos[n], s1 = g_epos[n + 1];

    float sum = 0.0f;
    float4 acc = make_float4(0.f, 0.f, 0.f, 0.f);
    int i = s0;

    for (; i + 3 < s1; i += 4) {
        int2 e0 = g_csr[i];
        int2 e1 = g_csr[i + 1];
        int2 e2 = g_csr[i + 2];
        int2 e3 = g_csr[i + 3];
        uint2 u0 = *(const uint2*)(g_Kh + (size_t)e0.x * (HD/2) + l * 2);
        uint2 u1 = *(const uint2*)(g_Kh + (size_t)e1.x * (HD/2) + l * 2);
        uint2 u2 = *(const uint2*)(g_Kh + (size_t)e2.x * (HD/2) + l * 2);
        uint2 u3 = *(const uint2*)(g_Kh + (size_t)e3.x * (HD/2) + l * 2);
        float4 w0 = *((const float4*)(g_V + (size_t)e0.x * HD) + l);
        float4 w1 = *((const float4*)(g_V + (size_t)e1.x * HD) + l);
        float4 w2 = *((const float4*)(g_V + (size_t)e2.x * HD) + l);
        float4 w3 = *((const float4*)(g_V + (size_t)e3.x * HD) + l);

        float2 a00 = bf2f(u0.x), a01 = bf2f(u0.y);
        float2 a10 = bf2f(u1.x), a11 = bf2f(u1.y);
        float2 a20 = bf2f(u2.x), a21 = bf2f(u2.y);
        float2 a30 = bf2f(u3.x), a31 = bf2f(u3.y);
        const float* p0 = &Psh[wid][e0.y][l*4];
        const float* p1 = &Psh[wid][e1.y][l*4];
        const float* p2 = &Psh[wid][e2.y][l*4];
        const float* p3 = &Psh[wid][e3.y][l*4];
        float v0 = a00.x * p0[0] + a00.y * p0[1] + a01.x * p0[2] + a01.y * p0[3];
        float v1 = a10.x * p1[0] + a10.y * p1[1] + a11.x * p1[2] + a11.y * p1[3];
        float v2 = a20.x * p2[0] + a20.y * p2[1] + a21.x * p2[2] + a21.y * p2[3];
        float v3 = a30.x * p3[0] + a30.y * p3[1] + a31.x * p3[2] + a31.y * p3[3];
        #pragma unroll
        for (int o = 16; o > 0; o >>= 1) {
            v0 += __shfl_xor_sync(0xffffffffu, v0, o);
            v1 += __shfl_xor_sync(0xffffffffu, v1, o);
            v2 += __shfl_xor_sync(0xffffffffu, v2, o);
            v3 += __shfl_xor_sync(0xffffffffu, v3, o);
        }
        float ex0 = __expf(v0);
        float ex1 = __expf(v1);
        float ex2 = __expf(v2);
        float ex3 = __expf(v3);
        sum += (ex0 + ex1) + (ex2 + ex3);
        acc.x += ex0 * w0.x + ex1 * w1.x + ex2 * w2.x + ex3 * w3.x;
        acc.y += ex0 * w0.y + ex1 * w1.y + ex2 * w2.y + ex3 * w3.y;
        acc.z += ex0 * w0.z + ex1 * w1.z + ex2 * w2.z + ex3 * w3.z;
        acc.w += ex0 * w0.w + ex1 * w1.w + ex2 * w2.w + ex3 * w3.w;
    }
    for (; i < s1; i++) {
        int2 e = g_csr[i];
        uint2 u = *(const uint2*)(g_Kh + (size_t)e.x * (HD/2) + l * 2);
        float4 vv = *((const float4*)(g_V + (size_t)e.x * HD) + l);
        float2 k0 = bf2f(u.x), k1 = bf2f(u.y);
        const float* p = &Psh[wid][e.y][l*4];
        float v = k0.x * p[0] + k0.y * p[1] + k1.x * p[2] + k1.y * p[3];
        #pragma unroll
        for (int o = 16; o > 0; o >>= 1) v += __shfl_xor_sync(0xffffffffu, v, o);
        float ex = __expf(v);
        sum += ex;
        acc.x += ex * vv.x; acc.y += ex * vv.y; acc.z += ex * vv.z; acc.w += ex * vv.w;
    }
    float inv = 1.0f / (sum + 1e-10f);
    acc.x *= inv; acc.y *= inv; acc.z *= inv; acc.w *= inv;
    *((float4*)(out + (size_t)n * HD) + l) = acc;
}

extern "C" void kernel_launch(void* const* d_in, const int* in_sizes, int n_in,
                              void* d_out, int out_size) {
    const float* x   = (const float*)d_in[0];
    const int*   ei  = (const int*)  d_in[1];
    const int*   ety = (const int*)  d_in[2];
    const int*   nty = (const int*)  d_in[3];
    const float* WQ  = (const float*)d_in[4];
    const float* WK  = (const float*)d_in[5];
    const float* WV  = (const float*)d_in[6];
    const float* We  = (const float*)d_in[7];
    const float* mu  = (const float*)d_in[8];
    float* out = (float*)d_out;

    int N = in_sizes[3];
    int E = in_sizes[2];
    const int* src = ei;
    const int* dst = ei + E;

    int nb = (N + 255) / 256;

    k_init<<<(N + NT * 128 + 255) / 256, 256>>>(N);
    k_hist<<<(E + 255) / 256, 256>>>(nty, dst, N, E);
    k_prefix<<<1, 1>>>();
    k_scatter<<<(N + 255) / 256, 256>>>(nty, N);
    k_transpose<<<(3 * NT * HD * HD + 255) / 256, 256>>>(WQ, WK, WV);

    k_scan_block<<<nb, 256>>>(N);
    k_scan_top<<<1, 256>>>(nb, E, N);
    k_scan_add<<<nb, 256>>>(N);
    k_escatter<<<(E + 255) / 256, 256>>>(src, dst, ety, E);

    k_qkv_mma<<<(N + 127) / 128 + NT, 256>>>(x, N);
    k_p_mma<<<(N + 127) / 128, 256>>>(We, N);

    k_edge<<<(N + 7) / 8, 256>>>(mu, out, N);
}